// round 5
// baseline (speedup 1.0000x reference)
#include <cuda_runtime.h>
#include <cstdint>

// Problem dims (fixed by the dataset)
#define BB   64
#define TT   1000
#define INN  512
#define HH   512
#define MM   (BB * TT)   // 64000

// Scratch
__device__ float g_Wx[MM * HH];        // 131 MB  GEMM output

__device__ __forceinline__ float tf32_rn(float x) {
    uint32_t b;
    asm("cvt.rna.tf32.f32 %0, %1;" : "=r"(b) : "f"(x));
    return __uint_as_float(b);
}

// ---------------------------------------------------------------------------
// Kernel 1: 3xTF32 GEMM via mma.sync m16n8k8.  Wx[m,n] = sum_k x[m,k] W[n,k]
//   Tile 128x128x16, 512 threads (16 warps, 4/SMSP), warp tile 64x16.
//   Double-buffered smem (2 x 40KB), register-staged global loads prefetched
//   2 chunks ahead. hi/lo tf32 split on the smem store.
// ---------------------------------------------------------------------------
#define GBM 128
#define GBN 128
#define GBK 16
#define LDP 20                       // (20g+tg) mod 32 covers all banks
#define NCHNK (INN / GBK)            // 32
#define TILE_F (GBM * LDP)           // 2560 floats per array
#define STAGE_F (4 * TILE_F)         // As_hi|As_lo|Bs_hi|Bs_lo
#define GEMM_SMEM (2 * STAGE_F * 4)  // 81920 bytes

#define MMA_TF32(d, a, b)                                                     \
    asm volatile(                                                             \
        "mma.sync.aligned.m16n8k8.row.col.f32.tf32.tf32.f32 "                 \
        "{%0,%1,%2,%3},{%4,%5,%6,%7},{%8,%9},{%0,%1,%2,%3};"                  \
        : "+f"((d)[0]), "+f"((d)[1]), "+f"((d)[2]), "+f"((d)[3])              \
        : "r"((a)[0]), "r"((a)[1]), "r"((a)[2]), "r"((a)[3]),                 \
          "r"((b)[0]), "r"((b)[1]))

__global__ void __launch_bounds__(512, 1) gemm3tf32_kernel(
    const float* __restrict__ X, const float* __restrict__ W)
{
    extern __shared__ __align__(16) float sm[];

    const int tid  = threadIdx.x;
    const int lane = tid & 31;
    const int wid  = tid >> 5;         // 0..15
    const int wm   = wid & 1;          // 2 m-warps of 64 rows
    const int wn   = wid >> 1;         // 8 n-warps of 16 cols
    const int g    = lane >> 2;        // group 0..7
    const int tg   = lane & 3;         // thread-in-group 0..3

    const int    n0 = blockIdx.x * GBN;          // n-tiles fastest -> X L2 reuse
    const size_t m0 = (size_t)blockIdx.y * GBM;

    // global-load mapping: 4 threads per row, each owns 4 consecutive floats
    const int grow = tid >> 2;          // 0..127
    const int gcol = (tid & 3) * 4;     // 0,4,8,12
    const float* Xp = X + (m0 + grow) * INN + gcol;
    const float* Wp = W + (size_t)(n0 + grow) * INN + gcol;

    float4 xa, wb;

    float acc[4][2][4];
    #pragma unroll
    for (int i = 0; i < 4; i++)
        #pragma unroll
        for (int j = 0; j < 2; j++)
            #pragma unroll
            for (int q = 0; q < 4; q++) acc[i][j][q] = 0.0f;

    auto gload = [&](int c) {
        const int k0 = c * GBK;
        xa = *(const float4*)(Xp + k0);
        wb = *(const float4*)(Wp + k0);
    };
    auto sstore = [&](int s) {
        float* As_hi = sm + s * STAGE_F;
        float* As_lo = As_hi + TILE_F;
        float* Bs_hi = As_lo + TILE_F;
        float* Bs_lo = Bs_hi + TILE_F;
        const int idx = grow * LDP + gcol;
        float4 hi, lo;
        hi.x = tf32_rn(xa.x); lo.x = tf32_rn(xa.x - hi.x);
        hi.y = tf32_rn(xa.y); lo.y = tf32_rn(xa.y - hi.y);
        hi.z = tf32_rn(xa.z); lo.z = tf32_rn(xa.z - hi.z);
        hi.w = tf32_rn(xa.w); lo.w = tf32_rn(xa.w - hi.w);
        *(float4*)(As_hi + idx) = hi;
        *(float4*)(As_lo + idx) = lo;
        hi.x = tf32_rn(wb.x); lo.x = tf32_rn(wb.x - hi.x);
        hi.y = tf32_rn(wb.y); lo.y = tf32_rn(wb.y - hi.y);
        hi.z = tf32_rn(wb.z); lo.z = tf32_rn(wb.z - hi.z);
        hi.w = tf32_rn(wb.w); lo.w = tf32_rn(wb.w - hi.w);
        *(float4*)(Bs_hi + idx) = hi;
        *(float4*)(Bs_lo + idx) = lo;
    };

    gload(0);
    sstore(0);
    gload(1);
    __syncthreads();

    for (int c = 0; c < NCHNK; c++) {
        const int cur = c & 1;
        if (c + 1 < NCHNK) sstore(1 - cur);   // overlaps MMA below
        if (c + 2 < NCHNK) gload(c + 2);      // overlaps MMA below

        const float* As_hi = sm + cur * STAGE_F;
        const float* As_lo = As_hi + TILE_F;
        const float* Bs_hi = As_lo + TILE_F;
        const float* Bs_lo = Bs_hi + TILE_F;

        #pragma unroll
        for (int ks = 0; ks < 2; ks++) {
            const int k0 = ks * 8;
            uint32_t ah[4][4], al[4][4], bh[2][2], bl[2][2];
            #pragma unroll
            for (int mb = 0; mb < 4; mb++) {
                const int r = (wm * 64 + mb * 16 + g) * LDP + k0 + tg;
                ah[mb][0] = __float_as_uint(As_hi[r]);
                ah[mb][1] = __float_as_uint(As_hi[r + 8 * LDP]);
                ah[mb][2] = __float_as_uint(As_hi[r + 4]);
                ah[mb][3] = __float_as_uint(As_hi[r + 8 * LDP + 4]);
                al[mb][0] = __float_as_uint(As_lo[r]);
                al[mb][1] = __float_as_uint(As_lo[r + 8 * LDP]);
                al[mb][2] = __float_as_uint(As_lo[r + 4]);
                al[mb][3] = __float_as_uint(As_lo[r + 8 * LDP + 4]);
            }
            #pragma unroll
            for (int nb = 0; nb < 2; nb++) {
                const int n = (wn * 16 + nb * 8 + g) * LDP + k0 + tg;
                bh[nb][0] = __float_as_uint(Bs_hi[n]);
                bh[nb][1] = __float_as_uint(Bs_hi[n + 4]);
                bl[nb][0] = __float_as_uint(Bs_lo[n]);
                bl[nb][1] = __float_as_uint(Bs_lo[n + 4]);
            }
            #pragma unroll
            for (int mb = 0; mb < 4; mb++)
                #pragma unroll
                for (int nb = 0; nb < 2; nb++) {
                    MMA_TF32(acc[mb][nb], ah[mb], bh[nb]);
                    MMA_TF32(acc[mb][nb], ah[mb], bl[nb]);
                    MMA_TF32(acc[mb][nb], al[mb], bh[nb]);
                }
        }
        __syncthreads();
    }

    // epilogue
    #pragma unroll
    for (int mb = 0; mb < 4; mb++) {
        const size_t r = m0 + wm * 64 + mb * 16 + g;
        #pragma unroll
        for (int nb = 0; nb < 2; nb++) {
            const int col = n0 + wn * 16 + nb * 8 + tg * 2;
            *(float2*)(g_Wx + r * HH + col) =
                make_float2(acc[mb][nb][0], acc[mb][nb][1]);
            *(float2*)(g_Wx + (r + 8) * HH + col) =
                make_float2(acc[mb][nb][2], acc[mb][nb][3]);
        }
    }
}

// ---------------------------------------------------------------------------
// Kernel 2: recurrent scan (unchanged from R4: 209us measured).
//   One CTA per batch, thread h owns neuron h. 2 barriers per firing step
//   (1 when silent). Gather reads V directly with MLP=8; diagonal term
//   removed by subtracting V[h][h] when self fired.
// ---------------------------------------------------------------------------
__global__ void __launch_bounds__(512, 1) scan_kernel(
    const float* __restrict__ alpha,
    const float* __restrict__ ut0,
    const float* __restrict__ st0,
    const float* __restrict__ V,
    float* __restrict__ out)
{
    const int b    = blockIdx.x;
    const int h    = threadIdx.x;
    const int lane = h & 31;
    const int wid  = h >> 5;

    __shared__ float    s_v[HH];
    __shared__ int      s_list[HH];
    __shared__ unsigned s_mask[16];

    const float a   = fminf(fmaxf(alpha[h], 0.81873075307798182f), 0.96078943915232320f);
    const float oma = 1.0f - a;
    const float vdiag = V[h * HH + h];

    float ut      = ut0[b * HH + h];
    float st_prev = st0[b * HH + h];

    s_v[h] = st_prev;
    __syncthreads();

    // Dense recurrent input for step 0 (continuous st0); remove diagonal term.
    float rec;
    {
        float r0 = 0.f, r1 = 0.f, r2 = 0.f, r3 = 0.f;
        #pragma unroll 4
        for (int j = 0; j < HH; j += 4) {
            r0 = fmaf(s_v[j + 0], V[(j + 0) * HH + h], r0);
            r1 = fmaf(s_v[j + 1], V[(j + 1) * HH + h], r1);
            r2 = fmaf(s_v[j + 2], V[(j + 2) * HH + h], r2);
            r3 = fmaf(s_v[j + 3], V[(j + 3) * HH + h], r3);
        }
        rec = ((r0 + r1) + (r2 + r3)) - st_prev * vdiag;
    }

    const float* wxp = g_Wx + (size_t)b * TT * HH + h;
    float*       op  = out  + (size_t)b * TT * HH + h;

    float wxb[8];
    #pragma unroll
    for (int i = 0; i < 8; i++) wxb[i] = __ldcs(wxp + (size_t)i * HH);

    for (int t0 = 0; t0 < TT; t0 += 8) {
        #pragma unroll
        for (int u = 0; u < 8; u++) {
            const int t = t0 + u;
            const float wx = wxb[u];
            if (t + 8 < TT) wxb[u] = __ldcs(wxp + (size_t)(t + 8) * HH);

            ut = a * (ut - st_prev) + oma * (wx + rec);
            const float st_new = (ut > 1.0f) ? 1.0f : 0.0f;
            __stcs(op + (size_t)t * HH, st_new);

            const bool fired = (st_new != 0.0f);
            const unsigned m = __ballot_sync(0xffffffffu, fired);
            if (lane == 0) s_mask[wid] = m;

            const int nf = __syncthreads_count(fired);   // barrier A (publishes s_mask)
            if (nf == 0) { rec = 0.0f; st_prev = st_new; continue; }

            int off = 0;
            #pragma unroll
            for (int w = 0; w < 16; w++)
                off += (w < wid) ? __popc(s_mask[w]) : 0;
            if (fired)
                s_list[off + __popc(m & ((1u << lane) - 1u))] = h;
            __syncthreads();                              // barrier B (list visible)

            float rr0 = 0.f, rr1 = 0.f, rr2 = 0.f, rr3 = 0.f;
            float rr4 = 0.f, rr5 = 0.f, rr6 = 0.f, rr7 = 0.f;
            int j = 0;
            for (; j + 8 <= nf; j += 8) {
                const int i0 = s_list[j + 0], i1 = s_list[j + 1];
                const int i2 = s_list[j + 2], i3 = s_list[j + 3];
                const int i4 = s_list[j + 4], i5 = s_list[j + 5];
                const int i6 = s_list[j + 6], i7 = s_list[j + 7];
                rr0 += __ldg(V + i0 * HH + h);
                rr1 += __ldg(V + i1 * HH + h);
                rr2 += __ldg(V + i2 * HH + h);
                rr3 += __ldg(V + i3 * HH + h);
                rr4 += __ldg(V + i4 * HH + h);
                rr5 += __ldg(V + i5 * HH + h);
                rr6 += __ldg(V + i6 * HH + h);
                rr7 += __ldg(V + i7 * HH + h);
            }
            for (; j < nf; j++) rr0 += __ldg(V + s_list[j] * HH + h);

            rec = (((rr0 + rr1) + (rr2 + rr3)) + ((rr4 + rr5) + (rr6 + rr7)))
                  - (fired ? vdiag : 0.0f);

            st_prev = st_new;
        }
    }
}

// ---------------------------------------------------------------------------
// Launch: inputs: x, W, V, alpha, ut0, st0, input_layer
// ---------------------------------------------------------------------------
extern "C" void kernel_launch(void* const* d_in, const int* in_sizes, int n_in,
                              void* d_out, int out_size) {
    const float* x     = (const float*)d_in[0];
    const float* W     = (const float*)d_in[1];
    const float* V     = (const float*)d_in[2];
    const float* alpha = (const float*)d_in[3];
    const float* ut0   = (const float*)d_in[4];
    const float* st0   = (const float*)d_in[5];
    float* out = (float*)d_out;

    cudaFuncSetAttribute(gemm3tf32_kernel,
                         cudaFuncAttributeMaxDynamicSharedMemorySize, GEMM_SMEM);

    dim3 ggrid(HH / GBN, MM / GBM);   // 4 x 500 (n-tiles fastest)
    gemm3tf32_kernel<<<ggrid, 512, GEMM_SMEM>>>(x, W);

    scan_kernel<<<BB, HH>>>(alpha, ut0, st0, V, out);
}

// round 6
// speedup vs baseline: 1.0192x; 1.0192x over previous
#include <cuda_runtime.h>
#include <cstdint>

// Problem dims (fixed by the dataset)
#define BB   64
#define TT   1000
#define INN  512
#define HH   512
#define MM   (BB * TT)   // 64000

// Scratch
__device__ float g_Wx[MM * HH];        // 131 MB  GEMM output
__device__ float g_Whi[HH * INN];      // 1 MB    tf32-hi of W
__device__ float g_Wlo[HH * INN];      // 1 MB    tf32-lo of W

__device__ __forceinline__ float tf32_rn(float x) {
    uint32_t b;
    asm("cvt.rna.tf32.f32 %0, %1;" : "=r"(b) : "f"(x));
    return __uint_as_float(b);
}

// cp.async helpers
__device__ __forceinline__ uint32_t smem_u32(const void* p) {
    uint32_t a;
    asm("{ .reg .u64 t; cvta.to.shared.u64 t, %1; cvt.u32.u64 %0, t; }"
        : "=r"(a) : "l"(p));
    return a;
}
__device__ __forceinline__ void cp_async16(uint32_t dst, const void* src) {
    asm volatile("cp.async.cg.shared.global [%0], [%1], 16;"
                 :: "r"(dst), "l"(src));
}
__device__ __forceinline__ void cp_commit() {
    asm volatile("cp.async.commit_group;" ::: "memory");
}
__device__ __forceinline__ void cp_wait1() {
    asm volatile("cp.async.wait_group 1;" ::: "memory");
}
__device__ __forceinline__ void cp_wait0() {
    asm volatile("cp.async.wait_group 0;" ::: "memory");
}

// ---------------------------------------------------------------------------
// Kernel 0: W -> tf32 hi/lo split (once; tiny)
// ---------------------------------------------------------------------------
__global__ void prep_w_kernel(const float* __restrict__ W) {
    int i = blockIdx.x * blockDim.x + threadIdx.x;
    if (i < HH * INN) {
        float w  = W[i];
        float hi = tf32_rn(w);
        g_Whi[i] = hi;
        g_Wlo[i] = tf32_rn(w - hi);
    }
}

// ---------------------------------------------------------------------------
// Kernel 1: 3xTF32 GEMM via mma.sync m16n8k8.  Wx[m,n] = sum_k x[m,k] W[n,k]
//   Tile 128x128x32, 256 threads, warp tile 64x32 (R4's proven shape).
//   3-stage cp.async pipeline: stage = A fp32 (18KB) + Bhi (18KB) + Blo (18KB).
//   A is hi/lo-split in registers at fragment-load time. One barrier/chunk,
//   fills of chunk c+2 overlap the MMA stream of chunk c.
// ---------------------------------------------------------------------------
#define GBM 128
#define GBN 128
#define GBK 32
#define LDP 36                        // (4g+tg) mod 32 -> conflict-free frags
#define NCHNK (INN / GBK)             // 16
#define NSTAGE 3
#define TILE_F (GBM * LDP)            // 4608 floats
#define STAGE_F (3 * TILE_F)          // A | Bhi | Blo
#define GEMM_SMEM (NSTAGE * STAGE_F * 4)   // 165888 bytes

#define MMA_TF32(d, a, b)                                                     \
    asm volatile(                                                             \
        "mma.sync.aligned.m16n8k8.row.col.f32.tf32.tf32.f32 "                 \
        "{%0,%1,%2,%3},{%4,%5,%6,%7},{%8,%9},{%0,%1,%2,%3};"                  \
        : "+f"((d)[0]), "+f"((d)[1]), "+f"((d)[2]), "+f"((d)[3])              \
        : "r"((a)[0]), "r"((a)[1]), "r"((a)[2]), "r"((a)[3]),                 \
          "r"((b)[0]), "r"((b)[1]))

__global__ void __launch_bounds__(256, 1) gemm3tf32_kernel(
    const float* __restrict__ X)
{
    extern __shared__ __align__(16) float sm[];
    const uint32_t smb = smem_u32(sm);

    const int tid  = threadIdx.x;
    const int lane = tid & 31;
    const int wm   = (tid >> 5) & 1;   // 2 m-warps of 64 rows
    const int wn   = tid >> 6;         // 4 n-warps of 32 cols
    const int g    = lane >> 2;        // group 0..7
    const int tg   = lane & 3;         // thread-in-group 0..3

    const int    n0 = blockIdx.x * GBN;          // n-tiles fastest -> X L2 reuse
    const size_t m0 = (size_t)blockIdx.y * GBM;

    // cp.async mapping: 2 threads per row, 4x16B segments each
    const int row  = tid >> 1;          // 0..127
    const int segb = (tid & 1) * 4;     // 0 or 4 (16B segment index)
    const float* Xp = X + (m0 + row) * INN + segb * 4;
    const float* Hp = g_Whi + (size_t)(n0 + row) * INN + segb * 4;
    const float* Lp = g_Wlo + (size_t)(n0 + row) * INN + segb * 4;
    const uint32_t dbase = smb + row * LDP * 4 + segb * 16;

    auto issue = [&](int c) {
        const int s = c % NSTAGE;
        const uint32_t d = dbase + s * STAGE_F * 4;
        const float* xs = Xp + c * GBK;
        const float* hs = Hp + c * GBK;
        const float* ls = Lp + c * GBK;
        #pragma unroll
        for (int i = 0; i < 4; i++) {
            cp_async16(d + i * 16,                  xs + i * 4);
            cp_async16(d + TILE_F * 4 + i * 16,     hs + i * 4);
            cp_async16(d + 2 * TILE_F * 4 + i * 16, ls + i * 4);
        }
    };

    float acc[4][4][4];
    #pragma unroll
    for (int i = 0; i < 4; i++)
        #pragma unroll
        for (int j = 0; j < 4; j++)
            #pragma unroll
            for (int q = 0; q < 4; q++) acc[i][j][q] = 0.0f;

    issue(0); cp_commit();
    issue(1); cp_commit();

    for (int c = 0; c < NCHNK; c++) {
        if (c == NCHNK - 1) cp_wait0(); else cp_wait1();
        __syncthreads();
        if (c + 2 < NCHNK) issue(c + 2);   // overlaps MMAs below
        cp_commit();

        const float* As = sm + (c % NSTAGE) * STAGE_F;
        const float* Bh = As + TILE_F;
        const float* Bl = As + 2 * TILE_F;

        #pragma unroll
        for (int ks = 0; ks < 4; ks++) {
            const int k0 = ks * 8;
            uint32_t ah[4][4], al[4][4], bh[4][2], bl[4][2];
            #pragma unroll
            for (int mb = 0; mb < 4; mb++) {
                const int r = (wm * 64 + mb * 16 + g) * LDP + k0 + tg;
                const float a0 = As[r];
                const float a1 = As[r + 8 * LDP];
                const float a2 = As[r + 4];
                const float a3 = As[r + 8 * LDP + 4];
                const float h0 = tf32_rn(a0), h1 = tf32_rn(a1);
                const float h2 = tf32_rn(a2), h3 = tf32_rn(a3);
                ah[mb][0] = __float_as_uint(h0);
                ah[mb][1] = __float_as_uint(h1);
                ah[mb][2] = __float_as_uint(h2);
                ah[mb][3] = __float_as_uint(h3);
                al[mb][0] = __float_as_uint(tf32_rn(a0 - h0));
                al[mb][1] = __float_as_uint(tf32_rn(a1 - h1));
                al[mb][2] = __float_as_uint(tf32_rn(a2 - h2));
                al[mb][3] = __float_as_uint(tf32_rn(a3 - h3));
            }
            #pragma unroll
            for (int nb = 0; nb < 4; nb++) {
                const int n = (wn * 32 + nb * 8 + g) * LDP + k0 + tg;
                bh[nb][0] = __float_as_uint(Bh[n]);
                bh[nb][1] = __float_as_uint(Bh[n + 4]);
                bl[nb][0] = __float_as_uint(Bl[n]);
                bl[nb][1] = __float_as_uint(Bl[n + 4]);
            }
            #pragma unroll
            for (int mb = 0; mb < 4; mb++)
                #pragma unroll
                for (int nb = 0; nb < 4; nb++) {
                    MMA_TF32(acc[mb][nb], ah[mb], bh[nb]);
                    MMA_TF32(acc[mb][nb], ah[mb], bl[nb]);
                    MMA_TF32(acc[mb][nb], al[mb], bh[nb]);
                }
        }
    }

    // epilogue
    #pragma unroll
    for (int mb = 0; mb < 4; mb++) {
        const size_t r = m0 + wm * 64 + mb * 16 + g;
        #pragma unroll
        for (int nb = 0; nb < 4; nb++) {
            const int col = n0 + wn * 32 + nb * 8 + tg * 2;
            *(float2*)(g_Wx + r * HH + col) =
                make_float2(acc[mb][nb][0], acc[mb][nb][1]);
            *(float2*)(g_Wx + (r + 8) * HH + col) =
                make_float2(acc[mb][nb][2], acc[mb][nb][3]);
        }
    }
}

// ---------------------------------------------------------------------------
// Kernel 2: recurrent scan (unchanged from R4: 208-209us measured twice).
// ---------------------------------------------------------------------------
__global__ void __launch_bounds__(512, 1) scan_kernel(
    const float* __restrict__ alpha,
    const float* __restrict__ ut0,
    const float* __restrict__ st0,
    const float* __restrict__ V,
    float* __restrict__ out)
{
    const int b    = blockIdx.x;
    const int h    = threadIdx.x;
    const int lane = h & 31;
    const int wid  = h >> 5;

    __shared__ float    s_v[HH];
    __shared__ int      s_list[HH];
    __shared__ unsigned s_mask[16];

    const float a   = fminf(fmaxf(alpha[h], 0.81873075307798182f), 0.96078943915232320f);
    const float oma = 1.0f - a;
    const float vdiag = V[h * HH + h];

    float ut      = ut0[b * HH + h];
    float st_prev = st0[b * HH + h];

    s_v[h] = st_prev;
    __syncthreads();

    // Dense recurrent input for step 0 (continuous st0); remove diagonal term.
    float rec;
    {
        float r0 = 0.f, r1 = 0.f, r2 = 0.f, r3 = 0.f;
        #pragma unroll 4
        for (int j = 0; j < HH; j += 4) {
            r0 = fmaf(s_v[j + 0], V[(j + 0) * HH + h], r0);
            r1 = fmaf(s_v[j + 1], V[(j + 1) * HH + h], r1);
            r2 = fmaf(s_v[j + 2], V[(j + 2) * HH + h], r2);
            r3 = fmaf(s_v[j + 3], V[(j + 3) * HH + h], r3);
        }
        rec = ((r0 + r1) + (r2 + r3)) - st_prev * vdiag;
    }

    const float* wxp = g_Wx + (size_t)b * TT * HH + h;
    float*       op  = out  + (size_t)b * TT * HH + h;

    float wxb[8];
    #pragma unroll
    for (int i = 0; i < 8; i++) wxb[i] = __ldcs(wxp + (size_t)i * HH);

    for (int t0 = 0; t0 < TT; t0 += 8) {
        #pragma unroll
        for (int u = 0; u < 8; u++) {
            const int t = t0 + u;
            const float wx = wxb[u];
            if (t + 8 < TT) wxb[u] = __ldcs(wxp + (size_t)(t + 8) * HH);

            ut = a * (ut - st_prev) + oma * (wx + rec);
            const float st_new = (ut > 1.0f) ? 1.0f : 0.0f;
            __stcs(op + (size_t)t * HH, st_new);

            const bool fired = (st_new != 0.0f);
            const unsigned m = __ballot_sync(0xffffffffu, fired);
            if (lane == 0) s_mask[wid] = m;

            const int nf = __syncthreads_count(fired);   // barrier A (publishes s_mask)
            if (nf == 0) { rec = 0.0f; st_prev = st_new; continue; }

            int off = 0;
            #pragma unroll
            for (int w = 0; w < 16; w++)
                off += (w < wid) ? __popc(s_mask[w]) : 0;
            if (fired)
                s_list[off + __popc(m & ((1u << lane) - 1u))] = h;
            __syncthreads();                              // barrier B (list visible)

            float rr0 = 0.f, rr1 = 0.f, rr2 = 0.f, rr3 = 0.f;
            float rr4 = 0.f, rr5 = 0.f, rr6 = 0.f, rr7 = 0.f;
            int j = 0;
            for (; j + 8 <= nf; j += 8) {
                const int i0 = s_list[j + 0], i1 = s_list[j + 1];
                const int i2 = s_list[j + 2], i3 = s_list[j + 3];
                const int i4 = s_list[j + 4], i5 = s_list[j + 5];
                const int i6 = s_list[j + 6], i7 = s_list[j + 7];
                rr0 += __ldg(V + i0 * HH + h);
                rr1 += __ldg(V + i1 * HH + h);
                rr2 += __ldg(V + i2 * HH + h);
                rr3 += __ldg(V + i3 * HH + h);
                rr4 += __ldg(V + i4 * HH + h);
                rr5 += __ldg(V + i5 * HH + h);
                rr6 += __ldg(V + i6 * HH + h);
                rr7 += __ldg(V + i7 * HH + h);
            }
            for (; j < nf; j++) rr0 += __ldg(V + s_list[j] * HH + h);

            rec = (((rr0 + rr1) + (rr2 + rr3)) + ((rr4 + rr5) + (rr6 + rr7)))
                  - (fired ? vdiag : 0.0f);

            st_prev = st_new;
        }
    }
}

// ---------------------------------------------------------------------------
// Launch: inputs: x, W, V, alpha, ut0, st0, input_layer
// ---------------------------------------------------------------------------
extern "C" void kernel_launch(void* const* d_in, const int* in_sizes, int n_in,
                              void* d_out, int out_size) {
    const float* x     = (const float*)d_in[0];
    const float* W     = (const float*)d_in[1];
    const float* V     = (const float*)d_in[2];
    const float* alpha = (const float*)d_in[3];
    const float* ut0   = (const float*)d_in[4];
    const float* st0   = (const float*)d_in[5];
    float* out = (float*)d_out;

    cudaFuncSetAttribute(gemm3tf32_kernel,
                         cudaFuncAttributeMaxDynamicSharedMemorySize, GEMM_SMEM);

    prep_w_kernel<<<(HH * INN + 255) / 256, 256>>>(W);

    dim3 ggrid(HH / GBN, MM / GBM);   // 4 x 500 (n-tiles fastest)
    gemm3tf32_kernel<<<ggrid, 256, GEMM_SMEM>>>(x);

    scan_kernel<<<BB, HH>>>(alpha, ut0, st0, V, out);
}

// round 7
// speedup vs baseline: 1.4673x; 1.4397x over previous
#include <cuda_runtime.h>
#include <cuda_fp16.h>
#include <cstdint>

// Problem dims (fixed by the dataset)
#define BB   64
#define TT   1000
#define INN  512
#define HH   512
#define MM   (BB * TT)   // 64000

// Scratch
__device__ float  g_Wx[MM * HH];       // 131 MB  GEMM output
__device__ __half g_Whi[HH * INN];     // 0.5 MB  fp16-hi of W
__device__ __half g_Wlo[HH * INN];     // 0.5 MB  fp16-lo of W

// cp.async helpers
__device__ __forceinline__ uint32_t smem_u32(const void* p) {
    uint32_t a;
    asm("{ .reg .u64 t; cvta.to.shared.u64 t, %1; cvt.u32.u64 %0, t; }"
        : "=r"(a) : "l"(p));
    return a;
}
__device__ __forceinline__ void cp_async16(uint32_t dst, const void* src) {
    asm volatile("cp.async.cg.shared.global [%0], [%1], 16;"
                 :: "r"(dst), "l"(src));
}
__device__ __forceinline__ void cp_commit() {
    asm volatile("cp.async.commit_group;" ::: "memory");
}
__device__ __forceinline__ void cp_wait0() {
    asm volatile("cp.async.wait_group 0;" ::: "memory");
}

// ---------------------------------------------------------------------------
// Kernel 0: W -> fp16 hi/lo split (once; tiny)
// ---------------------------------------------------------------------------
__global__ void prep_w_kernel(const float* __restrict__ W) {
    int i = blockIdx.x * blockDim.x + threadIdx.x;
    if (i < HH * INN) {
        float w   = W[i];
        __half hi = __float2half_rn(w);
        g_Whi[i]  = hi;
        g_Wlo[i]  = __float2half_rn(w - __half2float(hi));
    }
}

// ---------------------------------------------------------------------------
// Kernel 1: 2xFP16-split GEMM via mma.sync m16n8k16 (2x tf32 FLOP rate).
//   Wx[m,n] = sum_k x[m,k] W[n,k];  acc += Ah*Bh + Ah*Bl + Al*Bh  (fp32 accum)
//   Tile 128x128x64, 256 threads, warp tile 64x32, double-buffered smem.
//   X: register-staged fp32, split to fp16 hi/lo on the smem store.
//   W: precomputed fp16 planes via cp.async. One barrier per chunk.
// ---------------------------------------------------------------------------
#define GBM 128
#define GBN 128
#define GBK 64
#define LDPH 72                       // halfs per row: (36w+tg) conflict-free
#define NCHNK (INN / GBK)             // 8
#define PLANE_H (GBM * LDPH)          // 9216 halfs per plane
#define STAGE_H (4 * PLANE_H)         // Ah | Al | Bh | Bl
#define GEMM_SMEM (2 * STAGE_H * 2)   // 147456 bytes

#define MMA_F16(d, a, b)                                                      \
    asm volatile(                                                             \
        "mma.sync.aligned.m16n8k16.row.col.f32.f16.f16.f32 "                  \
        "{%0,%1,%2,%3},{%4,%5,%6,%7},{%8,%9},{%0,%1,%2,%3};"                  \
        : "+f"((d)[0]), "+f"((d)[1]), "+f"((d)[2]), "+f"((d)[3])              \
        : "r"((a)[0]), "r"((a)[1]), "r"((a)[2]), "r"((a)[3]),                 \
          "r"((b)[0]), "r"((b)[1]))

__global__ void __launch_bounds__(256, 1) gemm2fp16_kernel(
    const float* __restrict__ X)
{
    extern __shared__ __align__(16) __half smh[];
    const uint32_t smb = smem_u32(smh);

    const int tid  = threadIdx.x;
    const int lane = tid & 31;
    const int wm   = (tid >> 5) & 1;   // 2 m-warps of 64 rows
    const int wn   = tid >> 6;         // 4 n-warps of 32 cols
    const int g    = lane >> 2;        // group 0..7
    const int tg   = lane & 3;         // thread-in-group 0..3

    const int    n0 = blockIdx.x * GBN;          // n-tiles fastest -> X L2 reuse
    const size_t m0 = (size_t)blockIdx.y * GBM;

    // X staging: 2 threads per row, each 32 consecutive floats (8 float4)
    const int xrow = tid >> 1;          // 0..127
    const int xcol = (tid & 1) * 32;    // 0 or 32
    const float* Xp = X + (m0 + xrow) * INN + xcol;

    // W cp.async: 2 threads per row, each 4x16B segments per plane
    const int wrow = tid >> 1;
    const int wseg = (tid & 1) * 4;     // 16B segment base (0 or 4)
    const __half* Hp = g_Whi + (size_t)(n0 + wrow) * INN + wseg * 8;
    const __half* Lp = g_Wlo + (size_t)(n0 + wrow) * INN + wseg * 8;
    const uint32_t wdst = smb + (2 * PLANE_H + wrow * LDPH) * 2 + wseg * 16;

    float4 xa[8];
    auto gload = [&](int c) {
        const int k0 = c * GBK;
        #pragma unroll
        for (int i = 0; i < 8; i++)
            xa[i] = *(const float4*)(Xp + k0 + 4 * i);
    };
    auto wissue = [&](int c, int s) {
        const uint32_t d = wdst + s * STAGE_H * 2;
        const __half* hs = Hp + c * GBK;
        const __half* ls = Lp + c * GBK;
        #pragma unroll
        for (int i = 0; i < 4; i++) {
            cp_async16(d + i * 16,               hs + i * 8);
            cp_async16(d + PLANE_H * 2 + i * 16, ls + i * 8);
        }
    };
    auto sstore = [&](int s) {
        __half* Ah = smh + s * STAGE_H;
        __half* Al = Ah + PLANE_H;
        const int idx = xrow * LDPH + xcol;
        #pragma unroll
        for (int i = 0; i < 8; i++) {
            const float4 v = xa[i];
            const __half2 h0 = __floats2half2_rn(v.x, v.y);
            const __half2 h1 = __floats2half2_rn(v.z, v.w);
            const __half2 l0 = __floats2half2_rn(v.x - __low2float(h0),
                                                 v.y - __high2float(h0));
            const __half2 l1 = __floats2half2_rn(v.z - __low2float(h1),
                                                 v.w - __high2float(h1));
            *(__half2*)(Ah + idx + 4 * i)     = h0;
            *(__half2*)(Ah + idx + 4 * i + 2) = h1;
            *(__half2*)(Al + idx + 4 * i)     = l0;
            *(__half2*)(Al + idx + 4 * i + 2) = l1;
        }
    };

    float acc[4][4][4];
    #pragma unroll
    for (int i = 0; i < 4; i++)
        #pragma unroll
        for (int j = 0; j < 4; j++)
            #pragma unroll
            for (int q = 0; q < 4; q++) acc[i][j][q] = 0.0f;

    // prologue: fill buffer 0, preload regs for chunk 1
    wissue(0, 0); cp_commit();
    gload(0);
    sstore(0);
    gload(1);
    cp_wait0();
    __syncthreads();

    for (int c = 0; c < NCHNK; c++) {
        const int cur = c & 1;
        if (c + 1 < NCHNK) {
            wissue(c + 1, 1 - cur);           // async, overlaps MMAs
            cp_commit();
            sstore(1 - cur);                  // X chunk c+1 from regs
        }
        if (c + 2 < NCHNK) gload(c + 2);      // refill regs

        const uint32_t* Ah32 = (const uint32_t*)(smh + cur * STAGE_H);
        const uint32_t* Al32 = Ah32 + PLANE_H / 2;
        const uint32_t* Bh32 = Ah32 + PLANE_H;       // 2*PLANE_H halfs
        const uint32_t* Bl32 = Ah32 + 3 * PLANE_H / 2;

        #pragma unroll
        for (int ks = 0; ks < 4; ks++) {
            const int kw = ks * 8 + tg;       // word offset within row
            uint32_t ah[4][4], al[4][4], bh[4][2], bl[4][2];
            #pragma unroll
            for (int mb = 0; mb < 4; mb++) {
                const int r = (wm * 64 + mb * 16 + g) * (LDPH / 2) + kw;
                ah[mb][0] = Ah32[r];
                ah[mb][1] = Ah32[r + 8 * (LDPH / 2)];
                ah[mb][2] = Ah32[r + 4];
                ah[mb][3] = Ah32[r + 8 * (LDPH / 2) + 4];
                al[mb][0] = Al32[r];
                al[mb][1] = Al32[r + 8 * (LDPH / 2)];
                al[mb][2] = Al32[r + 4];
                al[mb][3] = Al32[r + 8 * (LDPH / 2) + 4];
            }
            #pragma unroll
            for (int nb = 0; nb < 4; nb++) {
                const int n = (wn * 32 + nb * 8 + g) * (LDPH / 2) + kw;
                bh[nb][0] = Bh32[n];
                bh[nb][1] = Bh32[n + 4];
                bl[nb][0] = Bl32[n];
                bl[nb][1] = Bl32[n + 4];
            }
            #pragma unroll
            for (int mb = 0; mb < 4; mb++)
                #pragma unroll
                for (int nb = 0; nb < 4; nb++) {
                    MMA_F16(acc[mb][nb], ah[mb], bh[nb]);
                    MMA_F16(acc[mb][nb], ah[mb], bl[nb]);
                    MMA_F16(acc[mb][nb], al[mb], bh[nb]);
                }
        }
        cp_wait0();
        __syncthreads();
    }

    // epilogue (C frag layout identical to k8 case)
    #pragma unroll
    for (int mb = 0; mb < 4; mb++) {
        const size_t r = m0 + wm * 64 + mb * 16 + g;
        #pragma unroll
        for (int nb = 0; nb < 4; nb++) {
            const int col = n0 + wn * 32 + nb * 8 + tg * 2;
            *(float2*)(g_Wx + r * HH + col) =
                make_float2(acc[mb][nb][0], acc[mb][nb][1]);
            *(float2*)(g_Wx + (r + 8) * HH + col) =
                make_float2(acc[mb][nb][2], acc[mb][nb][3]);
        }
    }
}

// ---------------------------------------------------------------------------
// Kernel 2: recurrent scan (unchanged from R4: 208-209us measured twice).
// ---------------------------------------------------------------------------
__global__ void __launch_bounds__(512, 1) scan_kernel(
    const float* __restrict__ alpha,
    const float* __restrict__ ut0,
    const float* __restrict__ st0,
    const float* __restrict__ V,
    float* __restrict__ out)
{
    const int b    = blockIdx.x;
    const int h    = threadIdx.x;
    const int lane = h & 31;
    const int wid  = h >> 5;

    __shared__ float    s_v[HH];
    __shared__ int      s_list[HH];
    __shared__ unsigned s_mask[16];

    const float a   = fminf(fmaxf(alpha[h], 0.81873075307798182f), 0.96078943915232320f);
    const float oma = 1.0f - a;
    const float vdiag = V[h * HH + h];

    float ut      = ut0[b * HH + h];
    float st_prev = st0[b * HH + h];

    s_v[h] = st_prev;
    __syncthreads();

    // Dense recurrent input for step 0 (continuous st0); remove diagonal term.
    float rec;
    {
        float r0 = 0.f, r1 = 0.f, r2 = 0.f, r3 = 0.f;
        #pragma unroll 4
        for (int j = 0; j < HH; j += 4) {
            r0 = fmaf(s_v[j + 0], V[(j + 0) * HH + h], r0);
            r1 = fmaf(s_v[j + 1], V[(j + 1) * HH + h], r1);
            r2 = fmaf(s_v[j + 2], V[(j + 2) * HH + h], r2);
            r3 = fmaf(s_v[j + 3], V[(j + 3) * HH + h], r3);
        }
        rec = ((r0 + r1) + (r2 + r3)) - st_prev * vdiag;
    }

    const float* wxp = g_Wx + (size_t)b * TT * HH + h;
    float*       op  = out  + (size_t)b * TT * HH + h;

    float wxb[8];
    #pragma unroll
    for (int i = 0; i < 8; i++) wxb[i] = __ldcs(wxp + (size_t)i * HH);

    for (int t0 = 0; t0 < TT; t0 += 8) {
        #pragma unroll
        for (int u = 0; u < 8; u++) {
            const int t = t0 + u;
            const float wx = wxb[u];
            if (t + 8 < TT) wxb[u] = __ldcs(wxp + (size_t)(t + 8) * HH);

            ut = a * (ut - st_prev) + oma * (wx + rec);
            const float st_new = (ut > 1.0f) ? 1.0f : 0.0f;
            __stcs(op + (size_t)t * HH, st_new);

            const bool fired = (st_new != 0.0f);
            const unsigned m = __ballot_sync(0xffffffffu, fired);
            if (lane == 0) s_mask[wid] = m;

            const int nf = __syncthreads_count(fired);   // barrier A (publishes s_mask)
            if (nf == 0) { rec = 0.0f; st_prev = st_new; continue; }

            int off = 0;
            #pragma unroll
            for (int w = 0; w < 16; w++)
                off += (w < wid) ? __popc(s_mask[w]) : 0;
            if (fired)
                s_list[off + __popc(m & ((1u << lane) - 1u))] = h;
            __syncthreads();                              // barrier B (list visible)

            float rr0 = 0.f, rr1 = 0.f, rr2 = 0.f, rr3 = 0.f;
            float rr4 = 0.f, rr5 = 0.f, rr6 = 0.f, rr7 = 0.f;
            int j = 0;
            for (; j + 8 <= nf; j += 8) {
                const int i0 = s_list[j + 0], i1 = s_list[j + 1];
                const int i2 = s_list[j + 2], i3 = s_list[j + 3];
                const int i4 = s_list[j + 4], i5 = s_list[j + 5];
                const int i6 = s_list[j + 6], i7 = s_list[j + 7];
                rr0 += __ldg(V + i0 * HH + h);
                rr1 += __ldg(V + i1 * HH + h);
                rr2 += __ldg(V + i2 * HH + h);
                rr3 += __ldg(V + i3 * HH + h);
                rr4 += __ldg(V + i4 * HH + h);
                rr5 += __ldg(V + i5 * HH + h);
                rr6 += __ldg(V + i6 * HH + h);
                rr7 += __ldg(V + i7 * HH + h);
            }
            for (; j < nf; j++) rr0 += __ldg(V + s_list[j] * HH + h);

            rec = (((rr0 + rr1) + (rr2 + rr3)) + ((rr4 + rr5) + (rr6 + rr7)))
                  - (fired ? vdiag : 0.0f);

            st_prev = st_new;
        }
    }
}

// ---------------------------------------------------------------------------
// Launch: inputs: x, W, V, alpha, ut0, st0, input_layer
// ---------------------------------------------------------------------------
extern "C" void kernel_launch(void* const* d_in, const int* in_sizes, int n_in,
                              void* d_out, int out_size) {
    const float* x     = (const float*)d_in[0];
    const float* W     = (const float*)d_in[1];
    const float* V     = (const float*)d_in[2];
    const float* alpha = (const float*)d_in[3];
    const float* ut0   = (const float*)d_in[4];
    const float* st0   = (const float*)d_in[5];
    float* out = (float*)d_out;

    cudaFuncSetAttribute(gemm2fp16_kernel,
                         cudaFuncAttributeMaxDynamicSharedMemorySize, GEMM_SMEM);

    prep_w_kernel<<<(HH * INN + 255) / 256, 256>>>(W);

    dim3 ggrid(HH / GBN, MM / GBM);   // 4 x 500 (n-tiles fastest)
    gemm2fp16_kernel<<<ggrid, 256, GEMM_SMEM>>>(x);

    scan_kernel<<<BB, HH>>>(alpha, ut0, st0, V, out);
}

// round 8
// speedup vs baseline: 1.4679x; 1.0004x over previous
#include <cuda_runtime.h>
#include <cuda_fp16.h>
#include <cstdint>

// Problem dims (fixed by the dataset)
#define BB   64
#define TT   1000
#define INN  512
#define HH   512
#define MM   (BB * TT)   // 64000

// Scratch
__device__ float  g_Wx[MM * HH];       // 131 MB  GEMM output
__device__ __half g_Whi[HH * INN];     // 0.5 MB  fp16-hi of W
__device__ __half g_Wlo[HH * INN];     // 0.5 MB  fp16-lo of W

// cp.async helpers
__device__ __forceinline__ uint32_t smem_u32(const void* p) {
    uint32_t a;
    asm("{ .reg .u64 t; cvta.to.shared.u64 t, %1; cvt.u32.u64 %0, t; }"
        : "=r"(a) : "l"(p));
    return a;
}
__device__ __forceinline__ void cp_async16(uint32_t dst, const void* src) {
    asm volatile("cp.async.cg.shared.global [%0], [%1], 16;"
                 :: "r"(dst), "l"(src));
}
__device__ __forceinline__ void cp_commit() {
    asm volatile("cp.async.commit_group;" ::: "memory");
}
__device__ __forceinline__ void cp_wait0() {
    asm volatile("cp.async.wait_group 0;" ::: "memory");
}

// ---------------------------------------------------------------------------
// Kernel 0: W -> fp16 hi/lo split (once; tiny)
// ---------------------------------------------------------------------------
__global__ void prep_w_kernel(const float* __restrict__ W) {
    int i = blockIdx.x * blockDim.x + threadIdx.x;
    if (i < HH * INN) {
        float w   = W[i];
        __half hi = __float2half_rn(w);
        g_Whi[i]  = hi;
        g_Wlo[i]  = __float2half_rn(w - __half2float(hi));
    }
}

// ---------------------------------------------------------------------------
// Kernel 1: 2xFP16-split GEMM via mma.sync m16n8k16.
//   Wx[m,n] = sum_k x[m,k] W[n,k];  acc += Ah*Bh + Ah*Bl + Al*Bh  (fp32 accum)
//   Tile 128x128x64, 256 threads, warp tile 64x32, double-buffered smem.
//   Product loop OUTERMOST: 16 independent MMAs between same-acc reuses
//   (kills the hh->hl->lh RAW stall chain of R7).
// ---------------------------------------------------------------------------
#define GBM 128
#define GBN 128
#define GBK 64
#define LDPH 72                       // halfs per row: conflict-free frags
#define NCHNK (INN / GBK)             // 8
#define PLANE_H (GBM * LDPH)          // 9216 halfs per plane
#define STAGE_H (4 * PLANE_H)         // Ah | Al | Bh | Bl
#define GEMM_SMEM (2 * STAGE_H * 2)   // 147456 bytes

#define MMA_F16(d, a, b)                                                      \
    asm volatile(                                                             \
        "mma.sync.aligned.m16n8k16.row.col.f32.f16.f16.f32 "                  \
        "{%0,%1,%2,%3},{%4,%5,%6,%7},{%8,%9},{%0,%1,%2,%3};"                  \
        : "+f"((d)[0]), "+f"((d)[1]), "+f"((d)[2]), "+f"((d)[3])              \
        : "r"((a)[0]), "r"((a)[1]), "r"((a)[2]), "r"((a)[3]),                 \
          "r"((b)[0]), "r"((b)[1]))

__global__ void __launch_bounds__(256, 1) gemm2fp16_kernel(
    const float* __restrict__ X)
{
    extern __shared__ __align__(16) __half smh[];
    const uint32_t smb = smem_u32(smh);

    const int tid  = threadIdx.x;
    const int lane = tid & 31;
    const int wm   = (tid >> 5) & 1;   // 2 m-warps of 64 rows
    const int wn   = tid >> 6;         // 4 n-warps of 32 cols
    const int g    = lane >> 2;        // group 0..7
    const int tg   = lane & 3;         // thread-in-group 0..3

    const int    n0 = blockIdx.x * GBN;          // n-tiles fastest -> X L2 reuse
    const size_t m0 = (size_t)blockIdx.y * GBM;

    // X staging: 2 threads per row, each 32 consecutive floats (8 float4)
    const int xrow = tid >> 1;          // 0..127
    const int xcol = (tid & 1) * 32;    // 0 or 32
    const float* Xp = X + (m0 + xrow) * INN + xcol;

    // W cp.async: 2 threads per row, each 4x16B segments per plane
    const int wrow = tid >> 1;
    const int wseg = (tid & 1) * 4;     // 16B segment base (0 or 4)
    const __half* Hp = g_Whi + (size_t)(n0 + wrow) * INN + wseg * 8;
    const __half* Lp = g_Wlo + (size_t)(n0 + wrow) * INN + wseg * 8;
    const uint32_t wdst = smb + (2 * PLANE_H + wrow * LDPH) * 2 + wseg * 16;

    float4 xa[8];
    auto gload = [&](int c) {
        const int k0 = c * GBK;
        #pragma unroll
        for (int i = 0; i < 8; i++)
            xa[i] = *(const float4*)(Xp + k0 + 4 * i);
    };
    auto wissue = [&](int c, int s) {
        const uint32_t d = wdst + s * STAGE_H * 2;
        const __half* hs = Hp + c * GBK;
        const __half* ls = Lp + c * GBK;
        #pragma unroll
        for (int i = 0; i < 4; i++) {
            cp_async16(d + i * 16,               hs + i * 8);
            cp_async16(d + PLANE_H * 2 + i * 16, ls + i * 8);
        }
    };
    auto sstore = [&](int s) {
        __half* Ah = smh + s * STAGE_H;
        __half* Al = Ah + PLANE_H;
        const int idx = xrow * LDPH + xcol;
        #pragma unroll
        for (int i = 0; i < 8; i++) {
            const float4 v = xa[i];
            const __half2 h0 = __floats2half2_rn(v.x, v.y);
            const __half2 h1 = __floats2half2_rn(v.z, v.w);
            const __half2 l0 = __floats2half2_rn(v.x - __low2float(h0),
                                                 v.y - __high2float(h0));
            const __half2 l1 = __floats2half2_rn(v.z - __low2float(h1),
                                                 v.w - __high2float(h1));
            *(__half2*)(Ah + idx + 4 * i)     = h0;
            *(__half2*)(Ah + idx + 4 * i + 2) = h1;
            *(__half2*)(Al + idx + 4 * i)     = l0;
            *(__half2*)(Al + idx + 4 * i + 2) = l1;
        }
    };

    float acc[4][4][4];
    #pragma unroll
    for (int i = 0; i < 4; i++)
        #pragma unroll
        for (int j = 0; j < 4; j++)
            #pragma unroll
            for (int q = 0; q < 4; q++) acc[i][j][q] = 0.0f;

    // prologue: fill buffer 0, preload regs for chunk 1
    wissue(0, 0); cp_commit();
    gload(0);
    sstore(0);
    gload(1);
    cp_wait0();
    __syncthreads();

    for (int c = 0; c < NCHNK; c++) {
        const int cur = c & 1;
        if (c + 1 < NCHNK) {
            wissue(c + 1, 1 - cur);           // async, overlaps MMAs
            cp_commit();
            sstore(1 - cur);                  // X chunk c+1 from regs
        }
        if (c + 2 < NCHNK) gload(c + 2);      // refill regs

        const uint32_t* Ah32 = (const uint32_t*)(smh + cur * STAGE_H);
        const uint32_t* Al32 = Ah32 + PLANE_H / 2;
        const uint32_t* Bh32 = Ah32 + PLANE_H;       // 2*PLANE_H halfs
        const uint32_t* Bl32 = Ah32 + 3 * PLANE_H / 2;

        #pragma unroll
        for (int ks = 0; ks < 4; ks++) {
            const int kw = ks * 8 + tg;       // word offset within row
            uint32_t ah[4][4], al[4][4], bh[4][2], bl[4][2];
            #pragma unroll
            for (int mb = 0; mb < 4; mb++) {
                const int r = (wm * 64 + mb * 16 + g) * (LDPH / 2) + kw;
                ah[mb][0] = Ah32[r];
                ah[mb][1] = Ah32[r + 8 * (LDPH / 2)];
                ah[mb][2] = Ah32[r + 4];
                ah[mb][3] = Ah32[r + 8 * (LDPH / 2) + 4];
                al[mb][0] = Al32[r];
                al[mb][1] = Al32[r + 8 * (LDPH / 2)];
                al[mb][2] = Al32[r + 4];
                al[mb][3] = Al32[r + 8 * (LDPH / 2) + 4];
            }
            #pragma unroll
            for (int nb = 0; nb < 4; nb++) {
                const int n = (wn * 32 + nb * 8 + g) * (LDPH / 2) + kw;
                bh[nb][0] = Bh32[n];
                bh[nb][1] = Bh32[n + 4];
                bl[nb][0] = Bl32[n];
                bl[nb][1] = Bl32[n + 4];
            }
            // Product-outermost: 16 independent MMAs between same-acc reuses.
            // Per-acc operation order is still hh -> hl -> lh (same numerics).
            #pragma unroll
            for (int mb = 0; mb < 4; mb++)
                #pragma unroll
                for (int nb = 0; nb < 4; nb++)
                    MMA_F16(acc[mb][nb], ah[mb], bh[nb]);
            #pragma unroll
            for (int mb = 0; mb < 4; mb++)
                #pragma unroll
                for (int nb = 0; nb < 4; nb++)
                    MMA_F16(acc[mb][nb], ah[mb], bl[nb]);
            #pragma unroll
            for (int mb = 0; mb < 4; mb++)
                #pragma unroll
                for (int nb = 0; nb < 4; nb++)
                    MMA_F16(acc[mb][nb], al[mb], bh[nb]);
        }
        cp_wait0();
        __syncthreads();
    }

    // epilogue
    #pragma unroll
    for (int mb = 0; mb < 4; mb++) {
        const size_t r = m0 + wm * 64 + mb * 16 + g;
        #pragma unroll
        for (int nb = 0; nb < 4; nb++) {
            const int col = n0 + wn * 32 + nb * 8 + tg * 2;
            *(float2*)(g_Wx + r * HH + col) =
                make_float2(acc[mb][nb][0], acc[mb][nb][1]);
            *(float2*)(g_Wx + (r + 8) * HH + col) =
                make_float2(acc[mb][nb][2], acc[mb][nb][3]);
        }
    }
}

// ---------------------------------------------------------------------------
// Kernel 2: recurrent scan (unchanged: 208-209us measured across rounds).
// ---------------------------------------------------------------------------
__global__ void __launch_bounds__(512, 1) scan_kernel(
    const float* __restrict__ alpha,
    const float* __restrict__ ut0,
    const float* __restrict__ st0,
    const float* __restrict__ V,
    float* __restrict__ out)
{
    const int b    = blockIdx.x;
    const int h    = threadIdx.x;
    const int lane = h & 31;
    const int wid  = h >> 5;

    __shared__ float    s_v[HH];
    __shared__ int      s_list[HH];
    __shared__ unsigned s_mask[16];

    const float a   = fminf(fmaxf(alpha[h], 0.81873075307798182f), 0.96078943915232320f);
    const float oma = 1.0f - a;
    const float vdiag = V[h * HH + h];

    float ut      = ut0[b * HH + h];
    float st_prev = st0[b * HH + h];

    s_v[h] = st_prev;
    __syncthreads();

    // Dense recurrent input for step 0 (continuous st0); remove diagonal term.
    float rec;
    {
        float r0 = 0.f, r1 = 0.f, r2 = 0.f, r3 = 0.f;
        #pragma unroll 4
        for (int j = 0; j < HH; j += 4) {
            r0 = fmaf(s_v[j + 0], V[(j + 0) * HH + h], r0);
            r1 = fmaf(s_v[j + 1], V[(j + 1) * HH + h], r1);
            r2 = fmaf(s_v[j + 2], V[(j + 2) * HH + h], r2);
            r3 = fmaf(s_v[j + 3], V[(j + 3) * HH + h], r3);
        }
        rec = ((r0 + r1) + (r2 + r3)) - st_prev * vdiag;
    }

    const float* wxp = g_Wx + (size_t)b * TT * HH + h;
    float*       op  = out  + (size_t)b * TT * HH + h;

    float wxb[8];
    #pragma unroll
    for (int i = 0; i < 8; i++) wxb[i] = __ldcs(wxp + (size_t)i * HH);

    for (int t0 = 0; t0 < TT; t0 += 8) {
        #pragma unroll
        for (int u = 0; u < 8; u++) {
            const int t = t0 + u;
            const float wx = wxb[u];
            if (t + 8 < TT) wxb[u] = __ldcs(wxp + (size_t)(t + 8) * HH);

            ut = a * (ut - st_prev) + oma * (wx + rec);
            const float st_new = (ut > 1.0f) ? 1.0f : 0.0f;
            __stcs(op + (size_t)t * HH, st_new);

            const bool fired = (st_new != 0.0f);
            const unsigned m = __ballot_sync(0xffffffffu, fired);
            if (lane == 0) s_mask[wid] = m;

            const int nf = __syncthreads_count(fired);   // barrier A (publishes s_mask)
            if (nf == 0) { rec = 0.0f; st_prev = st_new; continue; }

            int off = 0;
            #pragma unroll
            for (int w = 0; w < 16; w++)
                off += (w < wid) ? __popc(s_mask[w]) : 0;
            if (fired)
                s_list[off + __popc(m & ((1u << lane) - 1u))] = h;
            __syncthreads();                              // barrier B (list visible)

            float rr0 = 0.f, rr1 = 0.f, rr2 = 0.f, rr3 = 0.f;
            float rr4 = 0.f, rr5 = 0.f, rr6 = 0.f, rr7 = 0.f;
            int j = 0;
            for (; j + 8 <= nf; j += 8) {
                const int i0 = s_list[j + 0], i1 = s_list[j + 1];
                const int i2 = s_list[j + 2], i3 = s_list[j + 3];
                const int i4 = s_list[j + 4], i5 = s_list[j + 5];
                const int i6 = s_list[j + 6], i7 = s_list[j + 7];
                rr0 += __ldg(V + i0 * HH + h);
                rr1 += __ldg(V + i1 * HH + h);
                rr2 += __ldg(V + i2 * HH + h);
                rr3 += __ldg(V + i3 * HH + h);
                rr4 += __ldg(V + i4 * HH + h);
                rr5 += __ldg(V + i5 * HH + h);
                rr6 += __ldg(V + i6 * HH + h);
                rr7 += __ldg(V + i7 * HH + h);
            }
            for (; j < nf; j++) rr0 += __ldg(V + s_list[j] * HH + h);

            rec = (((rr0 + rr1) + (rr2 + rr3)) + ((rr4 + rr5) + (rr6 + rr7)))
                  - (fired ? vdiag : 0.0f);

            st_prev = st_new;
        }
    }
}

// ---------------------------------------------------------------------------
// Launch: inputs: x, W, V, alpha, ut0, st0, input_layer
// ---------------------------------------------------------------------------
extern "C" void kernel_launch(void* const* d_in, const int* in_sizes, int n_in,
                              void* d_out, int out_size) {
    const float* x     = (const float*)d_in[0];
    const float* W     = (const float*)d_in[1];
    const float* V     = (const float*)d_in[2];
    const float* alpha = (const float*)d_in[3];
    const float* ut0   = (const float*)d_in[4];
    const float* st0   = (const float*)d_in[5];
    float* out = (float*)d_out;

    cudaFuncSetAttribute(gemm2fp16_kernel,
                         cudaFuncAttributeMaxDynamicSharedMemorySize, GEMM_SMEM);

    prep_w_kernel<<<(HH * INN + 255) / 256, 256>>>(W);

    dim3 ggrid(HH / GBN, MM / GBM);   // 4 x 500 (n-tiles fastest)
    gemm2fp16_kernel<<<ggrid, 256, GEMM_SMEM>>>(x);

    scan_kernel<<<BB, HH>>>(alpha, ut0, st0, V, out);
}